// round 16
// baseline (speedup 1.0000x reference)
#include <cuda_runtime.h>
#include <cuda_bf16.h>
#include <cuda_fp16.h>
#include <cuda_fp8.h>

#define NB 32
#define NN 1024
#define NF 128
#define EPSF 1e-15f
#define MU_F 0.01f
#define INV32 0.03125f   // 1/sqrt(1024)

// d_out layout (floats): [ out (32*2*128) | Ac (32*1024*1024) | out_adj (32*4) | mincut | ortho ]
#define OUT_OFF    0
#define AC_OFF     8192
#define OADJ_OFF   (8192 + (size_t)NB*NN*NN)
#define MINCUT_OFF (OADJ_OFF + NB*4)
#define ORTHO_OFF  (MINCUT_OFF + 1)

// -------- scratch (static __device__; no cudaMalloc) --------
static __device__ unsigned char g_adj8[(size_t)NB*NN*NN];   // fp8 adj (32MB)
static __device__ __half g_E16a[(size_t)NB*NN*NN];          // exp(Z) ping fp16 (64MB); also P16 target
static __device__ __half g_E16b[(size_t)NB*NN*NN];          // exp(Z) pong fp16 (64MB)
static __device__ float  g_d[NB*NN];
static __device__ float  g_uod[NB*NN];
static __device__ float  g_dder[NB*NN];
static __device__ float4 g_vec4[NB*NN];            // {u, uod, s0, s1}
static __device__ uint2  g_pv8[NB*NN];             // packed {bf16(u,uod), bf16(s0,s1)}
static __device__ float2 g_pu[NB*NN];              // {P_i, uod_i}
static __device__ float  g_rs[5][NB*NN];           // rowsum(exp(Z_t))
static __device__ float  g_bacc[NB][6];
static __device__ float  g_qacc[NB][8];
static __device__ float  g_scal[NB][2];            // coefP (= -4 f c), R (= -4 f)

__device__ __forceinline__ unsigned pack2(float x, float y) {
    __nv_bfloat162 h = __float22bfloat162_rn(make_float2(x, y));
    return *reinterpret_cast<unsigned*>(&h);
}
__device__ __forceinline__ float2 unpack2(unsigned u) {
    return __bfloat1622float2(*reinterpret_cast<__nv_bfloat162*>(&u));
}
__device__ __forceinline__ void ld8f16(float* o, const __half* p) {
    uint4 v = *reinterpret_cast<const uint4*>(p);
    float2 f;
    f = __half22float2(*reinterpret_cast<__half2*>(&v.x)); o[0]=f.x; o[1]=f.y;
    f = __half22float2(*reinterpret_cast<__half2*>(&v.y)); o[2]=f.x; o[3]=f.y;
    f = __half22float2(*reinterpret_cast<__half2*>(&v.z)); o[4]=f.x; o[5]=f.y;
    f = __half22float2(*reinterpret_cast<__half2*>(&v.w)); o[6]=f.x; o[7]=f.y;
}
__device__ __forceinline__ void st8f16(__half* p, const float* v) {
    uint4 u; __half2 h;
    h = __float22half2_rn(make_float2(v[0],v[1])); u.x = *reinterpret_cast<unsigned*>(&h);
    h = __float22half2_rn(make_float2(v[2],v[3])); u.y = *reinterpret_cast<unsigned*>(&h);
    h = __float22half2_rn(make_float2(v[4],v[5])); u.z = *reinterpret_cast<unsigned*>(&h);
    h = __float22half2_rn(make_float2(v[6],v[7])); u.w = *reinterpret_cast<unsigned*>(&h);
    *reinterpret_cast<uint4*>(p) = u;
}
// ---- fp8 e4m3 helpers (adj only) ----
__device__ __forceinline__ float2 f8x2_to_f2(unsigned short s) {
    __half2_raw h = __nv_cvt_fp8x2_to_halfraw2((__nv_fp8x2_storage_t)s, __NV_E4M3);
    return __half22float2(*reinterpret_cast<__half2*>(&h));
}
__device__ __forceinline__ unsigned short f2_to_f8x2(float x, float y) {
    return (unsigned short)__nv_cvt_float2_to_fp8x2(make_float2(x, y), __NV_SATFINITE, __NV_E4M3);
}
__device__ __forceinline__ void cvt4f8(float* o, unsigned v) {
    float2 f;
    f = f8x2_to_f2((unsigned short)(v & 0xFFFFu)); o[0]=f.x; o[1]=f.y;
    f = f8x2_to_f2((unsigned short)(v >> 16));     o[2]=f.x; o[3]=f.y;
}
__device__ __forceinline__ void cvt8f8(float* o, uint2 v) {
    cvt4f8(o, v.x); cvt4f8(o + 4, v.y);
}

// -------- K0: zero accumulators + pooled-out region --------
__global__ void kzero(float* __restrict__ dout) {
    int i = blockIdx.x * 256 + threadIdx.x;
    if (i < 4*NB*NN) (&g_rs[1][0])[i] = 0.f;
    if (i < NB*8)    (&g_qacc[0][0])[i] = 0.f;
    if (i < NB*2*NF) dout[i] = 0.f;
}

// -------- K1: degrees + fp8 conversion (warp per row) --------
__global__ void kdeg(const float* __restrict__ adj) {
    int row = blockIdx.x * 8 + (threadIdx.x >> 5);
    int lane = threadIdx.x & 31;
    const float4* a4 = (const float4*)(adj + (size_t)row * NN);
    unsigned* h8 = (unsigned*)(g_adj8 + (size_t)row * NN);
    float s = 0.f;
    #pragma unroll
    for (int i = 0; i < 8; i++) {
        float4 v = a4[lane + 32*i];
        s += (v.x + v.y) + (v.z + v.w);
        h8[lane + 32*i] = (unsigned)f2_to_f8x2(v.x, v.y)
                        | ((unsigned)f2_to_f8x2(v.z, v.w) << 16);
    }
    #pragma unroll
    for (int o = 16; o; o >>= 1) s += __shfl_xor_sync(0xffffffffu, s, o);
    if (lane == 0) g_d[row] = s;
}

// -------- K2: per-node vectors + per-batch small reductions --------
__global__ void kvec(const float* __restrict__ s_in) {
    int b = blockIdx.x, t = threadIdx.x;
    float acc[6] = {0.f,0.f,0.f,0.f,0.f,0.f};
    const float2* s2 = (const float2*)s_in;
    for (int n = t; n < NN; n += 256) {
        int idx = b*NN + n;
        float2 sl = s2[idx];
        float m  = fmaxf(sl.x, sl.y);
        float e0 = expf(sl.x - m), e1 = expf(sl.y - m);
        float inv = 1.f / (e0 + e1);
        float p0 = e0 * inv, p1 = e1 * inv;
        float d   = g_d[idx];
        float d2  = sqrtf(d + EPSF) + EPSF;
        float u   = (sl.y > sl.x) ? -INV32 : INV32;
        float uod = u / d2;
        float dd  = -0.5f * d2 / (d + EPSF);
        float g   = u * d2;
        g_vec4[idx] = make_float4(u, uod, p0, p1);
        g_pv8[idx]  = make_uint2(pack2(u, uod), pack2(p0, p1));
        g_uod[idx]  = uod;
        g_dder[idx] = dd;
        acc[0] += g*g;
        acc[1] += d*uod*uod;
        acc[2] += d*(p0*p0 + p1*p1);
        acc[3] += p0*p0;
        acc[4] += p0*p1;
        acc[5] += p1*p1;
    }
    __shared__ float sh[8][6];
    int lane = t & 31, w = t >> 5;
    #pragma unroll
    for (int k = 0; k < 6; k++) {
        float v = acc[k];
        #pragma unroll
        for (int o = 16; o; o >>= 1) v += __shfl_xor_sync(0xffffffffu, v, o);
        if (lane == 0) sh[w][k] = v;
    }
    __syncthreads();
    if (t < 6) {
        float v = 0.f;
        #pragma unroll
        for (int w2 = 0; w2 < 8; w2++) v += sh[w2][t];
        g_bacc[b][t] = v;
    }
}

// -------- K3: quad forms — fp8 adj, packed bf16 vecs, 4 rows/group, 128x512 per block --------
__global__ void __launch_bounds__(256) kquad() {
    __shared__ uint2 sv2[512];
    __shared__ float sac[7];
    int b     = blockIdx.x >> 4;
    int half  = (blockIdx.x >> 3) & 1;
    int rbase = (blockIdx.x & 7) * 128;
    int c_off = half * 512;
    int t = threadIdx.x;
    for (int n = t; n < 512; n += 256) sv2[n] = g_pv8[b*NN + c_off + n];
    if (t < 7) sac[t] = 0.f;
    __syncthreads();
    int g = t >> 3, lane = t & 7;
    int R0 = rbase + g * 4;
    float acc[4][4] = {};
    const unsigned char* base = g_adj8 + (size_t)b*NN*NN + c_off;
    for (int k = 0; k < 16; k++) {
        int c0 = lane*4 + k*32;
        uint4 p01 = *reinterpret_cast<const uint4*>(&sv2[c0]);
        uint4 p23 = *reinterpret_cast<const uint4*>(&sv2[c0+2]);
        float2 uo0 = unpack2(p01.x), ss0 = unpack2(p01.y);
        float2 uo1 = unpack2(p01.z), ss1 = unpack2(p01.w);
        float2 uo2 = unpack2(p23.x), ss2 = unpack2(p23.y);
        float2 uo3 = unpack2(p23.z), ss3 = unpack2(p23.w);
        #pragma unroll
        for (int j = 0; j < 4; j++) {
            unsigned u = *reinterpret_cast<const unsigned*>(base + (size_t)(R0+j)*NN + c0);
            float2 f0 = f8x2_to_f2((unsigned short)(u & 0xFFFFu));
            float2 f1 = f8x2_to_f2((unsigned short)(u >> 16));
            acc[j][0] += f0.x*uo0.x + f0.y*uo1.x + f1.x*uo2.x + f1.y*uo3.x;
            acc[j][1] += f0.x*uo0.y + f0.y*uo1.y + f1.x*uo2.y + f1.y*uo3.y;
            acc[j][2] += f0.x*ss0.x + f0.y*ss1.x + f1.x*ss2.x + f1.y*ss3.x;
            acc[j][3] += f0.x*ss0.y + f0.y*ss1.y + f1.x*ss2.y + f1.y*ss3.y;
        }
    }
    #pragma unroll
    for (int j = 0; j < 4; j++)
        #pragma unroll
        for (int v = 0; v < 4; v++)
            #pragma unroll
            for (int o = 4; o; o >>= 1)
                acc[j][v] += __shfl_down_sync(0xffffffffu, acc[j][v], o, 8);
    if (lane == 0) {
        float aa=0, ss=0, qq=0, o00=0, o01=0, o10=0, o11=0;
        #pragma unroll
        for (int j = 0; j < 4; j++) {
            float4 vp = g_vec4[b*NN + R0 + j];
            aa  += vp.x * acc[j][1];
            ss  += vp.y * acc[j][0];
            qq  += vp.y * acc[j][1];
            o00 += vp.z * acc[j][2]; o01 += vp.z * acc[j][3];
            o10 += vp.w * acc[j][2]; o11 += vp.w * acc[j][3];
        }
        atomicAdd(&sac[0], aa); atomicAdd(&sac[1], ss); atomicAdd(&sac[2], qq);
        atomicAdd(&sac[3], o00); atomicAdd(&sac[4], o01);
        atomicAdd(&sac[5], o10); atomicAdd(&sac[6], o11);
    }
    __syncthreads();
    if (t < 7) atomicAdd(&g_qacc[b][t], sac[t]);
}

// -------- K4: per-batch scalars + out_adj + losses --------
__global__ void kscal(float* __restrict__ dout) {
    int b = threadIdx.x;
    float a  = g_qacc[b][0], sc = g_qacc[b][1], qd = g_qacc[b][2];
    float den = g_bacc[b][0], dsum = g_bacc[b][1], md = g_bacc[b][2];
    float ss00 = g_bacc[b][3], ss01 = g_bacc[b][4], ss11 = g_bacc[b][5];
    float num = dsum - qd;
    float f = (float)NN * fabsf(num / (den + EPSF));
    float c = a + sc;
    g_scal[b][0] = -4.f * f * c;
    g_scal[b][1] = -4.f * f;
    float o00 = g_qacc[b][3], o01 = g_qacc[b][4], o10 = g_qacc[b][5], o11 = g_qacc[b][6];
    dout[OADJ_OFF + b*4 + 0] = o00;
    dout[OADJ_OFF + b*4 + 1] = o01;
    dout[OADJ_OFF + b*4 + 2] = o10;
    dout[OADJ_OFF + b*4 + 3] = o11;
    float mc = (o00 + o11) / md;
    float ssn = sqrtf(ss00*ss00 + 2.f*ss01*ss01 + ss11*ss11);
    const float isq = 0.7071067811865476f;
    float q00 = ss00/ssn - isq, q01 = ss01/ssn, q11 = ss11/ssn - isq;
    float ortho = sqrtf(q00*q00 + 2.f*q01*q01 + q11*q11);
    #pragma unroll
    for (int o = 16; o; o >>= 1) {
        mc    += __shfl_xor_sync(0xffffffffu, mc, o);
        ortho += __shfl_xor_sync(0xffffffffu, ortho, o);
    }
    if (b == 0) {
        dout[MINCUT_OFF] = -mc / (float)NB;
        dout[ORTHO_OFF]  = ortho / (float)NB;
    }
}

// -------- K5: pack {P_i, uod_i} --------
__global__ void kprep() {
    int i = blockIdx.x * 256 + threadIdx.x;
    int b = i >> 10;
    g_pu[i] = make_float2(g_scal[b][0] * g_dder[i], g_uod[i]);
}

// -------- K6: pooled features --------
__global__ void kpool(const float* __restrict__ x, float* __restrict__ dout) {
    int b  = blockIdx.x >> 4;
    int ch = blockIdx.x & 15;
    int t  = threadIdx.x;  // 128
    float a0 = 0.f, a1 = 0.f;
    int n0 = ch * 64;
    for (int n = n0; n < n0 + 64; n++) {
        float4 v = g_vec4[b*NN + n];
        float xv = x[((size_t)(b*NN + n)) * NF + t];
        a0 += v.z * xv;
        a1 += v.w * xv;
    }
    atomicAdd(&dout[(b*2 + 0)*NF + t], a0);
    atomicAdd(&dout[(b*2 + 1)*NF + t], a1);
}

// -------- K7: iteration 1 — E1 computed once, stored fp16, + rowsums --------
__global__ void __launch_bounds__(256) kiter1() {
    __shared__ float2 spu[NN];
    int b  = blockIdx.x >> 6;            // NB*64 blocks, 16 rows each
    int r0 = (blockIdx.x & 63) * 16;
    int t = threadIdx.x, w = t >> 5, lane = t & 31;
    for (int n = t; n < NN; n += 256) spu[n] = g_pu[b*NN + n];
    __syncthreads();
    float R = g_scal[b][1];
    #pragma unroll
    for (int rr = 0; rr < 2; rr++) {
        int ii = r0 + w + rr*8;
        size_t rowoff = ((size_t)b * NN + ii) * NN;
        float2 pui = spu[ii];
        float sum = 0.f;
        #pragma unroll
        for (int seg = 0; seg < 8; seg++) {
            int j0 = seg*128 + lane*4;
            float a[4];
            cvt4f8(a, *reinterpret_cast<const unsigned*>(g_adj8 + rowoff + j0));
            float e[4];
            #pragma unroll
            for (int l = 0; l < 4; l++) {
                int j = j0 + l;
                float2 puj = spu[j];
                float dJ = pui.x + puj.x + 2.f * R * pui.y * puj.y;
                if (j == ii) dJ = pui.x + R * pui.y * pui.y;
                e[l] = __expf(a[l] - MU_F * dJ);
                sum += e[l];
            }
            __half2 h0 = __float22half2_rn(make_float2(e[0], e[1]));
            __half2 h1 = __float22half2_rn(make_float2(e[2], e[3]));
            *reinterpret_cast<uint2*>(g_E16a + rowoff + j0) =
                make_uint2(*reinterpret_cast<unsigned*>(&h0), *reinterpret_cast<unsigned*>(&h1));
        }
        #pragma unroll
        for (int o = 16; o; o >>= 1) sum += __shfl_xor_sync(0xffffffffu, sum, o);
        if (lane == 0) g_rs[0][b*NN + ii] = sum;
    }
}

// -------- K8: fused iteration t>=2, symmetric tile-pair, fp16 E + fp8 adj --------
// FINAL=0: fp16 E in/out, packed-bf16 output staging.
// FINAL=1: fp16 E in, fp32 adj for dJ + product, writes P16 (= g_E16a reused).
template<int FINAL>
__global__ void __launch_bounds__(256, 5) kiterT(int src, int it, const float* __restrict__ adjf) {
    __shared__ unsigned sPack[64][65];  // [icol][jrow] of tile (J,I): (bf16 Ac, bf16 A)
    __shared__ unsigned sOutU[FINAL ? 64*65 : 32*65];  // staged output tile (J,I)
    __shared__ float sInvI[64], sInvJ[64];
    __shared__ float2 sPuI[64], sPuJ[64];

    const __half* __restrict__ Ehp = src ? g_E16b : g_E16a;
    __half* __restrict__ Ehn = src ? g_E16a : g_E16b;
    const float* __restrict__ rp = g_rs[it - 1];
    float* __restrict__ rn = g_rs[it];

    int pid = blockIdx.x % 136;
    int b   = blockIdx.x / 136;
    int I = 0, rem = pid, rl = 16;
    while (rem >= rl) { rem -= rl; rl--; I++; }
    int J = I + rem;
    I <<= 6; J <<= 6;
    bool diag = (I == J);
    int t = threadIdx.x;
    int r = t >> 2, q = t & 3;
    const size_t base = (size_t)b * NN * NN;
    float R = g_scal[b][1];

    if (t < 64) { sInvI[t] = 1.f / rp[b*NN + I + t]; sPuI[t] = g_pu[b*NN + I + t]; }
    else if (t < 128) { int j = t - 64; sInvJ[j] = 1.f / rp[b*NN + J + j]; sPuJ[j] = g_pu[b*NN + J + j]; }
    __syncthreads();

    // Phase A: tile (J,I), row J+r, cols I + (32m + 8q + l); stage packed (Ac,A)
    {
        float invj = sInvJ[r];
        #pragma unroll
        for (int m = 0; m < 2; m++) {
            int cb = 32*m + 8*q;
            size_t off = base + (size_t)(J + r) * NN + I + cb;
            float e[8], a[8];
            if (FINAL) {
                const float4* af4 = reinterpret_cast<const float4*>(adjf + off);
                float4 a0 = af4[0], a1 = af4[1];
                a[0]=a0.x; a[1]=a0.y; a[2]=a0.z; a[3]=a0.w;
                a[4]=a1.x; a[5]=a1.y; a[6]=a1.z; a[7]=a1.w;
            } else cvt8f8(a, *reinterpret_cast<const uint2*>(g_adj8 + off));
            ld8f16(e, Ehp + off);
            #pragma unroll
            for (int l = 0; l < 8; l++) {
                float ac = e[l] * a[l] * invj;
                sPack[cb + l][r] = pack2(ac, a[l]);
            }
        }
    }
    __syncthreads();

    float2 pui = sPuI[r];
    float Pi = pui.x, wi = pui.y;
    float invi = sInvI[r];
    float dJself = Pi + R * wi * wi;

    float rowI = 0.f;
    #pragma unroll
    for (int m = 0; m < 2; m++) {
        int cb = 32*m + 8*q;
        size_t off = base + (size_t)(I + r) * NN + J + cb;
        float e[8], a[8];
        if (!diag) {
            ld8f16(e, Ehp + off);
            if (FINAL) {
                const float4* af4 = reinterpret_cast<const float4*>(adjf + off);
                float4 a0 = af4[0], a1 = af4[1];
                a[0]=a0.x; a[1]=a0.y; a[2]=a0.z; a[3]=a0.w;
                a[4]=a1.x; a[5]=a1.y; a[6]=a1.z; a[7]=a1.w;
            } else cvt8f8(a, *reinterpret_cast<const uint2*>(g_adj8 + off));
        } else if (FINAL) {
            const float4* af4 = reinterpret_cast<const float4*>(adjf + off);
            float4 a0 = af4[0], a1 = af4[1];
            a[0]=a0.x; a[1]=a0.y; a[2]=a0.z; a[3]=a0.w;
            a[4]=a1.x; a[5]=a1.y; a[6]=a1.z; a[7]=a1.w;
        }
        float outv[8];
        float enPrev = 0.f;
        #pragma unroll
        for (int l = 0; l < 8; l++) {
            int j = cb + l;
            float2 pj = sPuJ[j];
            float qv = Pi + pj.x + 2.f * R * pj.y * wi;
            float acij, amij;
            if (diag) {
                float2 pa = unpack2(sPack[j][r]);
                acij = pa.x; amij = acij - pa.y;
            } else {
                acij = e[l] * a[l] * invi; amij = acij - a[l];
            }
            float2 pt = unpack2(sPack[r][j]);
            float amji = pt.x - pt.y;
            float dJv;
            if (diag && j == r) dJv = 2.f * amij + dJself;
            else                dJv = 2.f * (amij + amji) + qv;
            float enij = __expf(acij - MU_F * dJv);
            rowI += enij;
            outv[l] = FINAL ? enij * a[l] : enij;
            if (!diag) {
                float enji = __expf(pt.x - MU_F * dJv);
                if (FINAL) sOutU[j*65 + r] = __float_as_uint(enji);
                else { if (l & 1) sOutU[(j>>1)*65 + r] = pack2(enPrev, enji); else enPrev = enji; }
            }
        }
        st8f16((FINAL ? g_E16a : Ehn) + off, outv);
    }
    rowI += __shfl_xor_sync(0xffffffffu, rowI, 1);
    rowI += __shfl_xor_sync(0xffffffffu, rowI, 2);
    if (q == 0) atomicAdd(&rn[b*NN + I + r], rowI);

    if (!diag) {
        __syncthreads();
        // Phase D: writeback tile (J,I): row J+r, cols I + cb..
        float rowJ = 0.f;
        #pragma unroll
        for (int m = 0; m < 2; m++) {
            int cb = 32*m + 8*q;
            size_t off = base + (size_t)(J + r) * NN + I + cb;
            if (FINAL) {
                float v[8];
                #pragma unroll
                for (int l = 0; l < 8; l++) { v[l] = __uint_as_float(sOutU[r*65 + cb + l]); rowJ += v[l]; }
                const float4* af4 = reinterpret_cast<const float4*>(adjf + off);
                float4 a0 = af4[0], a1 = af4[1];
                float p[8] = {v[0]*a0.x, v[1]*a0.y, v[2]*a0.z, v[3]*a0.w,
                              v[4]*a1.x, v[5]*a1.y, v[6]*a1.z, v[7]*a1.w};
                st8f16(g_E16a + off, p);
            } else {
                float v[8];
                #pragma unroll
                for (int l2 = 0; l2 < 4; l2++) {
                    unsigned u0 = sOutU[(r>>1)*65 + cb + 2*l2];
                    unsigned u1 = sOutU[(r>>1)*65 + cb + 2*l2 + 1];
                    float2 p0 = unpack2(u0), p1 = unpack2(u1);
                    v[2*l2]   = (r & 1) ? p0.y : p0.x;
                    v[2*l2+1] = (r & 1) ? p1.y : p1.x;
                    rowJ += v[2*l2] + v[2*l2+1];
                }
                st8f16(Ehn + off, v);
            }
        }
        rowJ += __shfl_xor_sync(0xffffffffu, rowJ, 1);
        rowJ += __shfl_xor_sync(0xffffffffu, rowJ, 2);
        if (q == 0) atomicAdd(&rn[b*NN + J + r], rowJ);
    }
}

// -------- K9: final normalize: Ac = P16 * inv  (P16 lives in g_E16a) --------
__global__ void kfinal(float* __restrict__ dout) {
    int row = blockIdx.x, t = threadIdx.x;
    float inv = 1.f / g_rs[4][row];
    uint2 ev = ((const uint2*)(g_E16a + (size_t)row * NN))[t];
    float2 e0 = __half22float2(*reinterpret_cast<__half2*>(&ev.x));
    float2 e1 = __half22float2(*reinterpret_cast<__half2*>(&ev.y));
    ((float4*)(dout + AC_OFF + (size_t)row * NN))[t] =
        make_float4(e0.x*inv, e0.y*inv, e1.x*inv, e1.y*inv);
}

extern "C" void kernel_launch(void* const* d_in, const int* in_sizes, int n_in,
                              void* d_out, int out_size) {
    const float* x   = (const float*)d_in[0];
    const float* adj = (const float*)d_in[1];
    const float* s   = (const float*)d_in[2];
    float* dout = (float*)d_out;

    kzero<<<512, 256>>>(dout);
    kdeg<<<NB*NN/8, 256>>>(adj);
    kvec<<<NB, 256>>>(s);
    kquad<<<NB*16, 256>>>();
    kscal<<<1, 32>>>(dout);
    kprep<<<NB*NN/256, 256>>>();
    kpool<<<NB*16, 128>>>(x, dout);
    kiter1<<<NB*64, 256>>>();                // E1 -> g_E16a, rs0
    kiterT<0><<<NB*136, 256>>>(0, 1, adj);   // iter2: E16a -> E16b
    kiterT<0><<<NB*136, 256>>>(1, 2, adj);   // iter3: E16b -> E16a
    kiterT<0><<<NB*136, 256>>>(0, 3, adj);   // iter4: E16a -> E16b
    kiterT<1><<<NB*136, 256>>>(1, 4, adj);   // iter5: E16b -> P16 (in g_E16a)
    kfinal<<<NB*NN, 256>>>(dout);
}

// round 17
// speedup vs baseline: 1.1230x; 1.1230x over previous
#include <cuda_runtime.h>
#include <cuda_bf16.h>
#include <cuda_fp16.h>
#include <cuda_fp8.h>

#define NB 32
#define NN 1024
#define NF 128
#define EPSF 1e-15f
#define MU_F 0.01f
#define INV32 0.03125f   // 1/sqrt(1024)

// d_out layout (floats): [ out (32*2*128) | Ac (32*1024*1024) | out_adj (32*4) | mincut | ortho ]
#define OUT_OFF    0
#define AC_OFF     8192
#define OADJ_OFF   (8192 + (size_t)NB*NN*NN)
#define MINCUT_OFF (OADJ_OFF + NB*4)
#define ORTHO_OFF  (MINCUT_OFF + 1)

// -------- scratch (static __device__; no cudaMalloc) --------
static __device__ unsigned char g_adj8[(size_t)NB*NN*NN];   // fp8 adj (32MB)
static __device__ unsigned char g_E8a[(size_t)NB*NN*NN];    // exp(Z) ping fp8 (32MB)
static __device__ unsigned char g_E8b[(size_t)NB*NN*NN];    // exp(Z) pong fp8 (32MB)
static __device__ __half        g_P16[(size_t)NB*NN*NN];    // E5*adj fp16 (64MB)
static __device__ float  g_d[NB*NN];
static __device__ float  g_uod[NB*NN];
static __device__ float  g_dder[NB*NN];
static __device__ float4 g_vec4[NB*NN];            // {u, uod, s0, s1}
static __device__ uint2  g_pv8[NB*NN];             // packed {bf16(u,uod), bf16(s0,s1)}
static __device__ float2 g_pu[NB*NN];              // {P_i, uod_i}
static __device__ float  g_rs[5][NB*NN];           // rowsum(exp(Z_t))
static __device__ float  g_bacc[NB][6];
static __device__ float  g_qacc[NB][8];
static __device__ float  g_scal[NB][2];            // coefP (= -4 f c), R (= -4 f)

__device__ __forceinline__ unsigned pack2(float x, float y) {
    __nv_bfloat162 h = __float22bfloat162_rn(make_float2(x, y));
    return *reinterpret_cast<unsigned*>(&h);
}
__device__ __forceinline__ float2 unpack2(unsigned u) {
    return __bfloat1622float2(*reinterpret_cast<__nv_bfloat162*>(&u));
}
__device__ __forceinline__ void st8f16(__half* p, const float* v) {
    uint4 u; __half2 h;
    h = __float22half2_rn(make_float2(v[0],v[1])); u.x = *reinterpret_cast<unsigned*>(&h);
    h = __float22half2_rn(make_float2(v[2],v[3])); u.y = *reinterpret_cast<unsigned*>(&h);
    h = __float22half2_rn(make_float2(v[4],v[5])); u.z = *reinterpret_cast<unsigned*>(&h);
    h = __float22half2_rn(make_float2(v[6],v[7])); u.w = *reinterpret_cast<unsigned*>(&h);
    *reinterpret_cast<uint4*>(p) = u;
}
// ---- fp8 e4m3 helpers ----
__device__ __forceinline__ float2 f8x2_to_f2(unsigned short s) {
    __half2_raw h = __nv_cvt_fp8x2_to_halfraw2((__nv_fp8x2_storage_t)s, __NV_E4M3);
    return __half22float2(*reinterpret_cast<__half2*>(&h));
}
__device__ __forceinline__ unsigned short f2_to_f8x2(float x, float y) {
    return (unsigned short)__nv_cvt_float2_to_fp8x2(make_float2(x, y), __NV_SATFINITE, __NV_E4M3);
}
__device__ __forceinline__ void cvt4f8(float* o, unsigned v) {
    float2 f;
    f = f8x2_to_f2((unsigned short)(v & 0xFFFFu)); o[0]=f.x; o[1]=f.y;
    f = f8x2_to_f2((unsigned short)(v >> 16));     o[2]=f.x; o[3]=f.y;
}
__device__ __forceinline__ void cvt8f8(float* o, uint2 v) {
    cvt4f8(o, v.x); cvt4f8(o + 4, v.y);
}
__device__ __forceinline__ void st8f8(unsigned char* p, const float* v) {
    unsigned lo = (unsigned)f2_to_f8x2(v[0],v[1]) | ((unsigned)f2_to_f8x2(v[2],v[3]) << 16);
    unsigned hi = (unsigned)f2_to_f8x2(v[4],v[5]) | ((unsigned)f2_to_f8x2(v[6],v[7]) << 16);
    *reinterpret_cast<uint2*>(p) = make_uint2(lo, hi);
}

// -------- K0: zero accumulators + pooled-out region --------
__global__ void kzero(float* __restrict__ dout) {
    int i = blockIdx.x * 256 + threadIdx.x;
    if (i < 4*NB*NN) (&g_rs[1][0])[i] = 0.f;
    if (i < NB*8)    (&g_qacc[0][0])[i] = 0.f;
    if (i < NB*2*NF) dout[i] = 0.f;
}

// -------- K1: degrees + fp8 conversion (warp per row) --------
__global__ void kdeg(const float* __restrict__ adj) {
    int row = blockIdx.x * 8 + (threadIdx.x >> 5);
    int lane = threadIdx.x & 31;
    const float4* a4 = (const float4*)(adj + (size_t)row * NN);
    unsigned* h8 = (unsigned*)(g_adj8 + (size_t)row * NN);
    float s = 0.f;
    #pragma unroll
    for (int i = 0; i < 8; i++) {
        float4 v = a4[lane + 32*i];
        s += (v.x + v.y) + (v.z + v.w);
        h8[lane + 32*i] = (unsigned)f2_to_f8x2(v.x, v.y)
                        | ((unsigned)f2_to_f8x2(v.z, v.w) << 16);
    }
    #pragma unroll
    for (int o = 16; o; o >>= 1) s += __shfl_xor_sync(0xffffffffu, s, o);
    if (lane == 0) g_d[row] = s;
}

// -------- K2: per-node vectors + per-batch small reductions --------
__global__ void kvec(const float* __restrict__ s_in) {
    int b = blockIdx.x, t = threadIdx.x;
    float acc[6] = {0.f,0.f,0.f,0.f,0.f,0.f};
    const float2* s2 = (const float2*)s_in;
    for (int n = t; n < NN; n += 256) {
        int idx = b*NN + n;
        float2 sl = s2[idx];
        float m  = fmaxf(sl.x, sl.y);
        float e0 = expf(sl.x - m), e1 = expf(sl.y - m);
        float inv = 1.f / (e0 + e1);
        float p0 = e0 * inv, p1 = e1 * inv;
        float d   = g_d[idx];
        float d2  = sqrtf(d + EPSF) + EPSF;
        float u   = (sl.y > sl.x) ? -INV32 : INV32;
        float uod = u / d2;
        float dd  = -0.5f * d2 / (d + EPSF);
        float g   = u * d2;
        g_vec4[idx] = make_float4(u, uod, p0, p1);
        g_pv8[idx]  = make_uint2(pack2(u, uod), pack2(p0, p1));
        g_uod[idx]  = uod;
        g_dder[idx] = dd;
        acc[0] += g*g;
        acc[1] += d*uod*uod;
        acc[2] += d*(p0*p0 + p1*p1);
        acc[3] += p0*p0;
        acc[4] += p0*p1;
        acc[5] += p1*p1;
    }
    __shared__ float sh[8][6];
    int lane = t & 31, w = t >> 5;
    #pragma unroll
    for (int k = 0; k < 6; k++) {
        float v = acc[k];
        #pragma unroll
        for (int o = 16; o; o >>= 1) v += __shfl_xor_sync(0xffffffffu, v, o);
        if (lane == 0) sh[w][k] = v;
    }
    __syncthreads();
    if (t < 6) {
        float v = 0.f;
        #pragma unroll
        for (int w2 = 0; w2 < 8; w2++) v += sh[w2][t];
        g_bacc[b][t] = v;
    }
}

// -------- K3: quad forms — fp8 adj, 4 rows/group, 128 rows x 256 cols per block --------
__global__ void __launch_bounds__(256) kquad() {
    __shared__ uint2 sv2[256];
    __shared__ float sac[7];
    int b       = blockIdx.x >> 5;          // NB*32 blocks
    int quarter = (blockIdx.x >> 3) & 3;
    int rbase   = (blockIdx.x & 7) * 128;
    int c_off   = quarter * 256;
    int t = threadIdx.x;
    if (t < 256) sv2[t] = g_pv8[b*NN + c_off + t];
    if (t < 7) sac[t] = 0.f;
    __syncthreads();
    int g = t >> 3, lane = t & 7;
    int R0 = rbase + g * 4;
    float acc[4][4] = {};
    const unsigned char* base = g_adj8 + (size_t)b*NN*NN + c_off;
    for (int k = 0; k < 8; k++) {
        int c0 = lane*4 + k*32;
        uint4 p01 = *reinterpret_cast<const uint4*>(&sv2[c0]);
        uint4 p23 = *reinterpret_cast<const uint4*>(&sv2[c0+2]);
        float2 uo0 = unpack2(p01.x), ss0 = unpack2(p01.y);
        float2 uo1 = unpack2(p01.z), ss1 = unpack2(p01.w);
        float2 uo2 = unpack2(p23.x), ss2 = unpack2(p23.y);
        float2 uo3 = unpack2(p23.z), ss3 = unpack2(p23.w);
        #pragma unroll
        for (int j = 0; j < 4; j++) {
            unsigned u = *reinterpret_cast<const unsigned*>(base + (size_t)(R0+j)*NN + c0);
            float2 f0 = f8x2_to_f2((unsigned short)(u & 0xFFFFu));
            float2 f1 = f8x2_to_f2((unsigned short)(u >> 16));
            acc[j][0] += f0.x*uo0.x + f0.y*uo1.x + f1.x*uo2.x + f1.y*uo3.x;
            acc[j][1] += f0.x*uo0.y + f0.y*uo1.y + f1.x*uo2.y + f1.y*uo3.y;
            acc[j][2] += f0.x*ss0.x + f0.y*ss1.x + f1.x*ss2.x + f1.y*ss3.x;
            acc[j][3] += f0.x*ss0.y + f0.y*ss1.y + f1.x*ss2.y + f1.y*ss3.y;
        }
    }
    #pragma unroll
    for (int j = 0; j < 4; j++)
        #pragma unroll
        for (int v = 0; v < 4; v++)
            #pragma unroll
            for (int o = 4; o; o >>= 1)
                acc[j][v] += __shfl_down_sync(0xffffffffu, acc[j][v], o, 8);
    if (lane == 0) {
        float aa=0, ss=0, qq=0, o00=0, o01=0, o10=0, o11=0;
        #pragma unroll
        for (int j = 0; j < 4; j++) {
            float4 vp = g_vec4[b*NN + R0 + j];
            aa  += vp.x * acc[j][1];
            ss  += vp.y * acc[j][0];
            qq  += vp.y * acc[j][1];
            o00 += vp.z * acc[j][2]; o01 += vp.z * acc[j][3];
            o10 += vp.w * acc[j][2]; o11 += vp.w * acc[j][3];
        }
        atomicAdd(&sac[0], aa); atomicAdd(&sac[1], ss); atomicAdd(&sac[2], qq);
        atomicAdd(&sac[3], o00); atomicAdd(&sac[4], o01);
        atomicAdd(&sac[5], o10); atomicAdd(&sac[6], o11);
    }
    __syncthreads();
    if (t < 7) atomicAdd(&g_qacc[b][t], sac[t]);
}

// -------- K4: per-batch scalars + out_adj + losses --------
__global__ void kscal(float* __restrict__ dout) {
    int b = threadIdx.x;
    float a  = g_qacc[b][0], sc = g_qacc[b][1], qd = g_qacc[b][2];
    float den = g_bacc[b][0], dsum = g_bacc[b][1], md = g_bacc[b][2];
    float ss00 = g_bacc[b][3], ss01 = g_bacc[b][4], ss11 = g_bacc[b][5];
    float num = dsum - qd;
    float f = (float)NN * fabsf(num / (den + EPSF));
    float c = a + sc;
    g_scal[b][0] = -4.f * f * c;
    g_scal[b][1] = -4.f * f;
    float o00 = g_qacc[b][3], o01 = g_qacc[b][4], o10 = g_qacc[b][5], o11 = g_qacc[b][6];
    dout[OADJ_OFF + b*4 + 0] = o00;
    dout[OADJ_OFF + b*4 + 1] = o01;
    dout[OADJ_OFF + b*4 + 2] = o10;
    dout[OADJ_OFF + b*4 + 3] = o11;
    float mc = (o00 + o11) / md;
    float ssn = sqrtf(ss00*ss00 + 2.f*ss01*ss01 + ss11*ss11);
    const float isq = 0.7071067811865476f;
    float q00 = ss00/ssn - isq, q01 = ss01/ssn, q11 = ss11/ssn - isq;
    float ortho = sqrtf(q00*q00 + 2.f*q01*q01 + q11*q11);
    #pragma unroll
    for (int o = 16; o; o >>= 1) {
        mc    += __shfl_xor_sync(0xffffffffu, mc, o);
        ortho += __shfl_xor_sync(0xffffffffu, ortho, o);
    }
    if (b == 0) {
        dout[MINCUT_OFF] = -mc / (float)NB;
        dout[ORTHO_OFF]  = ortho / (float)NB;
    }
}

// -------- K5: pack {P_i, uod_i} --------
__global__ void kprep() {
    int i = blockIdx.x * 256 + threadIdx.x;
    int b = i >> 10;
    g_pu[i] = make_float2(g_scal[b][0] * g_dder[i], g_uod[i]);
}

// -------- K6: pooled features --------
__global__ void kpool(const float* __restrict__ x, float* __restrict__ dout) {
    int b  = blockIdx.x >> 4;
    int ch = blockIdx.x & 15;
    int t  = threadIdx.x;  // 128
    float a0 = 0.f, a1 = 0.f;
    int n0 = ch * 64;
    for (int n = n0; n < n0 + 64; n++) {
        float4 v = g_vec4[b*NN + n];
        float xv = x[((size_t)(b*NN + n)) * NF + t];
        a0 += v.z * xv;
        a1 += v.w * xv;
    }
    atomicAdd(&dout[(b*2 + 0)*NF + t], a0);
    atomicAdd(&dout[(b*2 + 1)*NF + t], a1);
}

// -------- K7: iteration 1 rowsums ONLY (E1 recomputed in iter2), fp8 adj --------
__global__ void __launch_bounds__(256) kiter1() {
    __shared__ float2 spu[NN];
    int b  = blockIdx.x >> 6;            // NB*64 blocks, 16 rows each
    int r0 = (blockIdx.x & 63) * 16;
    int t = threadIdx.x, w = t >> 5, lane = t & 31;
    for (int n = t; n < NN; n += 256) spu[n] = g_pu[b*NN + n];
    __syncthreads();
    float R = g_scal[b][1];
    #pragma unroll
    for (int rr = 0; rr < 2; rr++) {
        int ii = r0 + w + rr*8;
        size_t rowoff = ((size_t)b * NN + ii) * NN;
        float2 pui = spu[ii];
        float sum = 0.f;
        #pragma unroll
        for (int seg = 0; seg < 8; seg++) {
            int j0 = seg*128 + lane*4;
            float a[4];
            cvt4f8(a, *reinterpret_cast<const unsigned*>(g_adj8 + rowoff + j0));
            #pragma unroll
            for (int l = 0; l < 4; l++) {
                int j = j0 + l;
                float2 puj = spu[j];
                float dJ = pui.x + puj.x + 2.f * R * pui.y * puj.y;
                if (j == ii) dJ = pui.x + R * pui.y * pui.y;
                sum += __expf(a[l] - MU_F * dJ);
            }
        }
        #pragma unroll
        for (int o = 16; o; o >>= 1) sum += __shfl_xor_sync(0xffffffffu, sum, o);
        if (lane == 0) g_rs[0][b*NN + ii] = sum;
    }
}

// -------- K8: fused iteration t>=2, symmetric tile-pair, fp8 E + fp8 adj --------
// RECOMP=1 (iter2): E1 recomputed from adj8, no E read.
// FINAL=0: fp8 in/out, packed-bf16 output staging (occ 6).
// FINAL=1: fp8 E in, fp32 adj for dJ + product, writes P16 = E5*adj fp16 (occ 5).
template<int FINAL, int RECOMP>
__global__ void __launch_bounds__(256, FINAL ? 5 : 6) kiterT(int src, int it, const float* __restrict__ adjf) {
    __shared__ unsigned sPack[64][65];  // [icol][jrow] of tile (J,I): (bf16 Ac, bf16 A)
    __shared__ unsigned sOutU[FINAL ? 64*65 : 32*65];  // staged output tile (J,I)
    __shared__ float sInvI[64], sInvJ[64];
    __shared__ float2 sPuI[64], sPuJ[64];

    const unsigned char* __restrict__ Ehp = src ? g_E8b : g_E8a;
    unsigned char* __restrict__ Ehn = src ? g_E8a : g_E8b;
    const float* __restrict__ rp = g_rs[it - 1];
    float* __restrict__ rn = g_rs[it];

    int pid = blockIdx.x % 136;
    int b   = blockIdx.x / 136;
    int I = 0, rem = pid, rl = 16;
    while (rem >= rl) { rem -= rl; rl--; I++; }
    int J = I + rem;
    I <<= 6; J <<= 6;
    bool diag = (I == J);
    int t = threadIdx.x;
    int r = t >> 2, q = t & 3;
    const size_t base = (size_t)b * NN * NN;
    float R = g_scal[b][1];

    if (t < 64) { sInvI[t] = 1.f / rp[b*NN + I + t]; sPuI[t] = g_pu[b*NN + I + t]; }
    else if (t < 128) { int j = t - 64; sInvJ[j] = 1.f / rp[b*NN + J + j]; sPuJ[j] = g_pu[b*NN + J + j]; }
    __syncthreads();

    // Phase A: tile (J,I), row J+r, cols I + (32m + 8q + l); stage packed (Ac,A)
    {
        float invj = sInvJ[r];
        float Pr = sPuJ[r].x, wr = sPuJ[r].y;
        #pragma unroll
        for (int m = 0; m < 2; m++) {
            int cb = 32*m + 8*q;
            size_t off = base + (size_t)(J + r) * NN + I + cb;
            float e[8], a[8];
            if (FINAL) {
                const float4* af4 = reinterpret_cast<const float4*>(adjf + off);
                float4 a0 = af4[0], a1 = af4[1];
                a[0]=a0.x; a[1]=a0.y; a[2]=a0.z; a[3]=a0.w;
                a[4]=a1.x; a[5]=a1.y; a[6]=a1.z; a[7]=a1.w;
            } else cvt8f8(a, *reinterpret_cast<const uint2*>(g_adj8 + off));
            if (!RECOMP) cvt8f8(e, *reinterpret_cast<const uint2*>(Ehp + off));
            #pragma unroll
            for (int l = 0; l < 8; l++) {
                float ev;
                if (RECOMP) {
                    float2 pc = sPuI[cb + l];
                    float d1 = Pr + pc.x + 2.f * R * wr * pc.y;
                    if (diag && r == cb + l) d1 = Pr + R * wr * wr;
                    ev = __expf(a[l] - MU_F * d1);
                } else ev = e[l];
                float ac = ev * a[l] * invj;
                sPack[cb + l][r] = pack2(ac, a[l]);
            }
        }
    }
    __syncthreads();

    float2 pui = sPuI[r];
    float Pi = pui.x, wi = pui.y;
    float invi = sInvI[r];
    float dJself = Pi + R * wi * wi;

    float rowI = 0.f;
    #pragma unroll
    for (int m = 0; m < 2; m++) {
        int cb = 32*m + 8*q;
        size_t off = base + (size_t)(I + r) * NN + J + cb;
        float e[8], a[8];
        if (!diag) {
            if (!RECOMP) cvt8f8(e, *reinterpret_cast<const uint2*>(Ehp + off));
            if (FINAL) {
                const float4* af4 = reinterpret_cast<const float4*>(adjf + off);
                float4 a0 = af4[0], a1 = af4[1];
                a[0]=a0.x; a[1]=a0.y; a[2]=a0.z; a[3]=a0.w;
                a[4]=a1.x; a[5]=a1.y; a[6]=a1.z; a[7]=a1.w;
            } else cvt8f8(a, *reinterpret_cast<const uint2*>(g_adj8 + off));
        } else if (FINAL) {
            const float4* af4 = reinterpret_cast<const float4*>(adjf + off);
            float4 a0 = af4[0], a1 = af4[1];
            a[0]=a0.x; a[1]=a0.y; a[2]=a0.z; a[3]=a0.w;
            a[4]=a1.x; a[5]=a1.y; a[6]=a1.z; a[7]=a1.w;
        }
        float outv[8];
        float enPrev = 0.f;
        #pragma unroll
        for (int l = 0; l < 8; l++) {
            int j = cb + l;
            float2 pj = sPuJ[j];
            float qv = Pi + pj.x + 2.f * R * pj.y * wi;
            float acij, amij;
            if (diag) {
                float2 pa = unpack2(sPack[j][r]);
                acij = pa.x; amij = acij - pa.y;
            } else {
                float ev;
                if (RECOMP) ev = __expf(a[l] - MU_F * qv);
                else        ev = e[l];
                acij = ev * a[l] * invi; amij = acij - a[l];
            }
            float2 pt = unpack2(sPack[r][j]);
            float amji = pt.x - pt.y;
            float dJv;
            if (diag && j == r) dJv = 2.f * amij + dJself;
            else                dJv = 2.f * (amij + amji) + qv;
            float enij = __expf(acij - MU_F * dJv);
            rowI += enij;
            outv[l] = FINAL ? enij * a[l] : enij;
            if (!diag) {
                float enji = __expf(pt.x - MU_F * dJv);
                if (FINAL) sOutU[j*65 + r] = __float_as_uint(enji);
                else { if (l & 1) sOutU[(j>>1)*65 + r] = pack2(enPrev, enji); else enPrev = enji; }
            }
        }
        if (FINAL) st8f16(g_P16 + off, outv);
        else       st8f8(Ehn + off, outv);
    }
    rowI += __shfl_xor_sync(0xffffffffu, rowI, 1);
    rowI += __shfl_xor_sync(0xffffffffu, rowI, 2);
    if (q == 0) atomicAdd(&rn[b*NN + I + r], rowI);

    if (!diag) {
        __syncthreads();
        // Phase D: writeback tile (J,I): row J+r, cols I + cb..
        float rowJ = 0.f;
        #pragma unroll
        for (int m = 0; m < 2; m++) {
            int cb = 32*m + 8*q;
            size_t off = base + (size_t)(J + r) * NN + I + cb;
            if (FINAL) {
                float v[8];
                #pragma unroll
                for (int l = 0; l < 8; l++) { v[l] = __uint_as_float(sOutU[r*65 + cb + l]); rowJ += v[l]; }
                const float4* af4 = reinterpret_cast<const float4*>(adjf + off);
                float4 a0 = af4[0], a1 = af4[1];
                float p[8] = {v[0]*a0.x, v[1]*a0.y, v[2]*a0.z, v[3]*a0.w,
                              v[4]*a1.x, v[5]*a1.y, v[6]*a1.z, v[7]*a1.w};
                st8f16(g_P16 + off, p);
            } else {
                float v[8];
                #pragma unroll
                for (int l2 = 0; l2 < 4; l2++) {
                    unsigned u0 = sOutU[(r>>1)*65 + cb + 2*l2];
                    unsigned u1 = sOutU[(r>>1)*65 + cb + 2*l2 + 1];
                    float2 p0 = unpack2(u0), p1 = unpack2(u1);
                    v[2*l2]   = (r & 1) ? p0.y : p0.x;
                    v[2*l2+1] = (r & 1) ? p1.y : p1.x;
                    rowJ += v[2*l2] + v[2*l2+1];
                }
                st8f8(Ehn + off, v);
            }
        }
        rowJ += __shfl_xor_sync(0xffffffffu, rowJ, 1);
        rowJ += __shfl_xor_sync(0xffffffffu, rowJ, 2);
        if (q == 0) atomicAdd(&rn[b*NN + J + r], rowJ);
    }
}

// -------- K9: final normalize: Ac = P16 * inv (wide: 8 elems/thread, 2 rows/block) --------
__global__ void __launch_bounds__(256) kfinal(float* __restrict__ dout) {
    int t = threadIdx.x;
    int row = blockIdx.x * 2 + (t >> 7);
    int c = (t & 127) * 8;
    float inv = 1.f / g_rs[4][row];
    uint4 ev = *reinterpret_cast<const uint4*>(g_P16 + (size_t)row * NN + c);
    float2 e0 = __half22float2(*reinterpret_cast<__half2*>(&ev.x));
    float2 e1 = __half22float2(*reinterpret_cast<__half2*>(&ev.y));
    float2 e2 = __half22float2(*reinterpret_cast<__half2*>(&ev.z));
    float2 e3 = __half22float2(*reinterpret_cast<__half2*>(&ev.w));
    float4* o4 = reinterpret_cast<float4*>(dout + AC_OFF + (size_t)row * NN + c);
    o4[0] = make_float4(e0.x*inv, e0.y*inv, e1.x*inv, e1.y*inv);
    o4[1] = make_float4(e2.x*inv, e2.y*inv, e3.x*inv, e3.y*inv);
}

extern "C" void kernel_launch(void* const* d_in, const int* in_sizes, int n_in,
                              void* d_out, int out_size) {
    const float* x   = (const float*)d_in[0];
    const float* adj = (const float*)d_in[1];
    const float* s   = (const float*)d_in[2];
    float* dout = (float*)d_out;

    kzero<<<512, 256>>>(dout);
    kdeg<<<NB*NN/8, 256>>>(adj);
    kvec<<<NB, 256>>>(s);
    kquad<<<NB*32, 256>>>();
    kscal<<<1, 32>>>(dout);
    kprep<<<NB*NN/256, 256>>>();
    kpool<<<NB*16, 128>>>(x, dout);
    kiter1<<<NB*64, 256>>>();
    kiterT<0,1><<<NB*136, 256>>>(0, 1, adj);  // iter2: recompute E1 -> E8b
    kiterT<0,0><<<NB*136, 256>>>(1, 2, adj);  // iter3: E8b -> E8a
    kiterT<0,0><<<NB*136, 256>>>(0, 3, adj);  // iter4: E8a -> E8b
    kiterT<1,0><<<NB*136, 256>>>(1, 4, adj);  // iter5: E8b -> P16 (fp16 E5*adj)
    kfinal<<<NB*NN/2, 256>>>(dout);
}